// round 13
// baseline (speedup 1.0000x reference)
#include <cuda_runtime.h>
#include <cuda_fp16.h>
#include <cstdint>

// ---------------------------------------------------------------------------
// Problem constants
// ---------------------------------------------------------------------------
constexpr int B_   = 8192;
constexpr int T_   = 658;
constexpr int I_   = 7;
constexpr int D1_  = 1024;
constexpr int D2_  = 512;
constexpr int D3_  = 128;
constexpr int XWT  = 688;
constexpr int TPAD = 672;

// ---------------------------------------------------------------------------
// Scratch
// ---------------------------------------------------------------------------
__device__ float   g_xw [(size_t)XWT * B_];
__device__ __half  g_ath[(size_t)B_ * TPAD];
__device__ __half  g_atl[(size_t)B_ * TPAD];

__device__ __half  g_w1h[(size_t)D1_ * TPAD];
__device__ __half  g_w2h[(size_t)D2_ * D1_ ];
__device__ __half  g_w3h[(size_t)D3_ * D2_ ];
__device__ __half  g_w4h[(size_t)T_  * D3_ ];

__device__ __half  g_y1h[(size_t)B_ * D1_], g_y1l[(size_t)B_ * D1_];
__device__ __half  g_y2h[(size_t)B_ * D2_], g_y2l[(size_t)B_ * D2_];
__device__ __half  g_y3h[(size_t)B_ * D3_], g_y3l[(size_t)B_ * D3_];

// ---------------------------------------------------------------------------
// PTX helpers
// ---------------------------------------------------------------------------
__device__ __forceinline__ uint32_t smem_u32(const void* p) {
    uint32_t a;
    asm("{ .reg .u64 t; cvta.to.shared.u64 t, %1; cvt.u32.u64 %0, t; }" : "=r"(a) : "l"(p));
    return a;
}

__device__ __forceinline__ void cp16(uint32_t dst, const void* src, int srcsize) {
    asm volatile("cp.async.cg.shared.global [%0], [%1], 16, %2;"
                 :: "r"(dst), "l"(src), "r"(srcsize));
}
#define CP_COMMIT() asm volatile("cp.async.commit_group;" ::: "memory")
#define CP_WAIT(n)  asm volatile("cp.async.wait_group %0;" :: "n"(n) : "memory")

#define LDSM4(r, a)                                                             \
    asm volatile("ldmatrix.sync.aligned.m8n8.x4.shared.b16 {%0,%1,%2,%3}, [%4];"\
                 : "=r"((r)[0]), "=r"((r)[1]), "=r"((r)[2]), "=r"((r)[3])       \
                 : "r"(a))

__device__ __forceinline__ void mma16816(float* d, const uint32_t* a,
                                         uint32_t b0, uint32_t b1) {
    asm volatile("mma.sync.aligned.m16n8k16.row.col.f32.f16.f16.f32 "
                 "{%0,%1,%2,%3}, {%4,%5,%6,%7}, {%8,%9}, {%0,%1,%2,%3};"
                 : "+f"(d[0]), "+f"(d[1]), "+f"(d[2]), "+f"(d[3])
                 : "r"(a[0]), "r"(a[1]), "r"(a[2]), "r"(a[3]), "r"(b0), "r"(b1));
}

// fp16-accumulator MMA (tests the f32-acc half-rate hypothesis)
__device__ __forceinline__ void mma16816h(uint32_t* d, const uint32_t* a,
                                          uint32_t b0, uint32_t b1) {
    asm volatile("mma.sync.aligned.m16n8k16.row.col.f16.f16.f16.f16 "
                 "{%0,%1}, {%2,%3,%4,%5}, {%6,%7}, {%0,%1};"
                 : "+r"(d[0]), "+r"(d[1])
                 : "r"(a[0]), "r"(a[1]), "r"(a[2]), "r"(a[3]), "r"(b0), "r"(b1));
}

// ---------------------------------------------------------------------------
// Stage 1: projection ([T,B] fp32)
// ---------------------------------------------------------------------------
__global__ void proj_kernel(const float* __restrict__ x,
                            const float* __restrict__ W_ih,
                            const float* __restrict__ b_ih,
                            const float* __restrict__ b_hh) {
    __shared__ float xs[32][225];
    const int t0 = blockIdx.x * 32;
    const int b0 = blockIdx.y * 32;
    const int tid = threadIdx.x;
    const int tlim = min(32, T_ - t0);
    const int nfl = tlim * I_;

    for (int i = tid; i < 32 * 224; i += 256) {
        int bl = i / 224;
        int off = i - bl * 224;
        float v = 0.f;
        if (off < nfl) v = x[((size_t)(b0 + bl) * T_ + t0) * I_ + off];
        xs[bl][off] = v;
    }
    __syncthreads();

    float w[7];
#pragma unroll
    for (int j = 0; j < 7; ++j) w[j] = W_ih[j];
    const float bias = b_ih[0] + b_hh[0];

    for (int i = tid; i < 1024; i += 256) {
        int bl = i & 31;
        int tl = i >> 5;
        if (tl < tlim) {
            const float* row = &xs[bl][tl * 7];
            float s = bias;
#pragma unroll
            for (int j = 0; j < 7; ++j) s = fmaf(row[j], w[j], s);
            g_xw[(size_t)(t0 + tl) * B_ + (b0 + bl)] = s;
        }
    }
}

// ---------------------------------------------------------------------------
// Stage 2: tanh recurrence -> fp16 hi/lo [B,TPAD]
// ---------------------------------------------------------------------------
__device__ __forceinline__ float tanh_fast(float xv) {
    float ax = fabsf(xv);
    float e = __expf(-2.0f * ax);
    float r = __fdividef(1.0f - e, 1.0f + e);
    return copysignf(r, xv);
}

__device__ __forceinline__ uint32_t pack_hilo(float v) {
    __half h = __float2half_rn(v);
    __half l = __float2half_rn(v - __half2float(h));
    return (uint32_t)__half_as_ushort(h) | ((uint32_t)__half_as_ushort(l) << 16);
}

__global__ void __launch_bounds__(256)
scan_kernel(const float* __restrict__ h0,
            const float* __restrict__ W_hh,
            float* __restrict__ hid) {
    __shared__ uint32_t sh[256][33];
    const int tid = threadIdx.x;
    const int b0 = blockIdx.x * 256;
    const int b  = b0 + tid;

    const float whh = W_hh[0];
    const float* xp = g_xw + b;
    float h = h0[b];
    float hT = h;

    float bufA[16], bufB[16];
#pragma unroll
    for (int j = 0; j < 16; ++j) bufA[j] = xp[(size_t)j * B_];

    for (int tc = 0; tc < TPAD; tc += 32) {
#pragma unroll
        for (int j = 0; j < 16; ++j) bufB[j] = xp[(size_t)(tc + 16 + j) * B_];
#pragma unroll
        for (int j = 0; j < 16; ++j) {
            h = tanh_fast(fmaf(h, whh, bufA[j]));
            sh[tid][j] = pack_hilo(h);
            if (tc + j == T_ - 1) hT = h;
        }
#pragma unroll
        for (int j = 0; j < 16; ++j) bufA[j] = xp[(size_t)(tc + 32 + j) * B_];
#pragma unroll
        for (int j = 0; j < 16; ++j) {
            h = tanh_fast(fmaf(h, whh, bufB[j]));
            sh[tid][16 + j] = pack_hilo(h);
            if (tc + 16 + j == T_ - 1) hT = h;
        }
        __syncthreads();
#pragma unroll
        for (int it = 0; it < 16; ++it) {
            int lin = it * 256 + tid;
            int r = lin >> 4;
            int p = lin & 15;
            uint32_t v0 = sh[r][2 * p];
            uint32_t v1 = sh[r][2 * p + 1];
            size_t o = (size_t)(b0 + r) * TPAD + tc + 2 * p;
            *(uint32_t*)(g_ath + o) = (v0 & 0xffffu) | (v1 << 16);
            *(uint32_t*)(g_atl + o) = (v0 >> 16) | (v1 & 0xffff0000u);
        }
        __syncthreads();
    }
    if (hid) hid[b] = hT;
}

// ---------------------------------------------------------------------------
// Weight conversion
// ---------------------------------------------------------------------------
__device__ __forceinline__ void cvt_seg(const float* __restrict__ src,
                                        __half* __restrict__ hi,
                                        int R, int K, int Kp, int i) {
    if (i < R * K) {
        int r = i / K, k = i - r * K;
        hi[(size_t)r * Kp + k] = __float2half_rn(src[i]);
    }
}

__global__ void cvt_all(const float* __restrict__ w1, const float* __restrict__ w2,
                        const float* __restrict__ w3, const float* __restrict__ w4) {
    int i = blockIdx.x * 256 + threadIdx.x;
    switch (blockIdx.y) {
        case 0: cvt_seg(w1, g_w1h, D1_, T_,  TPAD, i); break;
        case 1: cvt_seg(w2, g_w2h, D2_, D1_, D1_,  i); break;
        case 2: cvt_seg(w3, g_w3h, D3_, D2_, D2_,  i); break;
        case 3: cvt_seg(w4, g_w4h, T_,  D3_, D3_,  i); break;
    }
}

// ---------------------------------------------------------------------------
// Shared tiling constants
// ---------------------------------------------------------------------------
constexpr int PITCH  = 80;
constexpr int MATSZA = 128 * PITCH;                      // 10240
constexpr int STAGE_SZ_128 = 2 * MATSZA + 128 * PITCH;   // 30720
constexpr int STAGE_SZ_64  = 2 * MATSZA +  64 * PITCH;   // 25600
constexpr int SMEM_128_2   = 2 * STAGE_SZ_128;           // 61440
constexpr int SMEM_64_3    = 3 * STAGE_SZ_64;            // 76800

// ---------------------------------------------------------------------------
// Big GEMM (gemm1/gemm2): 256 thr, 8 warps 2(M)x4(N), warp tile 64x32, BN=128.
//   pass1 Ah*B -> f32 accum; pass2 Al*B -> f16 accum (half-rate test)
// ---------------------------------------------------------------------------
__device__ __forceinline__ void load_stage8(
        uint32_t sbase, int slot, int k0, int tid,
        const __half* Ah, const __half* Al, const __half* Bh,
        int K, int N, int bm, int bn) {
    const uint32_t dstb = sbase + slot * STAGE_SZ_128;
#pragma unroll
    for (int it = 0; it < 6; ++it) {
        int i = tid + it * 256;
        if (i < 1024) {
            int mat = i >> 9;
            int row = (i >> 2) & 127;
            int seg = i & 3;
            const __half* src = (mat == 0 ? Ah : Al) + (size_t)(bm + row) * K + k0 + seg * 8;
            cp16(dstb + mat * MATSZA + row * PITCH + seg * 16, src, 16);
        } else {
            int j = i - 1024;
            int row = j >> 2;
            int seg = j & 3;
            int n = bn + row;
            const __half* src;
            int size = 16;
            if (n < N) {
                src = Bh + (size_t)n * K + k0 + seg * 8;
            } else {
                src = Bh + k0 + seg * 8;
                size = 0;
            }
            cp16(dstb + 2 * MATSZA + row * PITCH + seg * 16, src, size);
        }
    }
}

template <bool RELU>
__global__ void __launch_bounds__(256)
gemm_big(const __half* __restrict__ Ah, const __half* __restrict__ Al,
         const __half* __restrict__ Bh,
         const float* __restrict__ bias,
         __half* __restrict__ Oh, __half* __restrict__ Ol,
         int K, int N, int strideO) {
    extern __shared__ char smem[];
    const uint32_t sbase = smem_u32(smem);
    const int tid = threadIdx.x;
    const int lane = tid & 31;
    const int wid = tid >> 5;
    const int wm = wid & 1;
    const int wn = wid >> 1;        // 0..3
    const int bm = blockIdx.x * 128;
    const int bn = blockIdx.y * 128;
    const int nk = K >> 5;

    float    acc32[4][4][4];
    uint32_t acc16[4][4][2];
#pragma unroll
    for (int i = 0; i < 4; ++i)
#pragma unroll
        for (int j = 0; j < 4; ++j) {
#pragma unroll
            for (int q = 0; q < 4; ++q) acc32[i][j][q] = 0.f;
            acc16[i][j][0] = 0u; acc16[i][j][1] = 0u;
        }

    const uint32_t a_addr = sbase + (wm * 64 + (lane & 15)) * PITCH + (lane >> 4) * 16;
    const uint32_t b_addr = sbase + 2 * MATSZA +
        (wn * 32 + (lane & 7) + ((lane >> 4) * 8)) * PITCH + ((lane >> 3) & 1) * 16;

    load_stage8(sbase, 0, 0, tid, Ah, Al, Bh, K, N, bm, bn);
    CP_COMMIT();

    for (int kc = 0; kc < nk; ++kc) {
        CP_WAIT(0);
        __syncthreads();
        if (kc + 1 < nk) {
            load_stage8(sbase, (kc + 1) & 1, (kc + 1) * 32, tid, Ah, Al, Bh, K, N, bm, bn);
            CP_COMMIT();
        }

        const uint32_t st = (uint32_t)(kc & 1) * STAGE_SZ_128;
#pragma unroll
        for (int kk = 0; kk < 2; ++kk) {
            const uint32_t ko = kk * 32;
            uint32_t aH[4][4], aL[4][4];
#pragma unroll
            for (int mi = 0; mi < 4; ++mi) {
                LDSM4(aH[mi], a_addr + st + mi * (16 * PITCH) + ko);
                LDSM4(aL[mi], a_addr + st + MATSZA + mi * (16 * PITCH) + ko);
            }
            uint32_t bR[2][4];
#pragma unroll
            for (int np = 0; np < 2; ++np)
                LDSM4(bR[np], b_addr + st + np * (16 * PITCH) + ko);
#pragma unroll
            for (int mi = 0; mi < 4; ++mi)
#pragma unroll
                for (int np = 0; np < 2; ++np) {
                    mma16816(acc32[mi][np * 2],     aH[mi], bR[np][0], bR[np][1]);
                    mma16816(acc32[mi][np * 2 + 1], aH[mi], bR[np][2], bR[np][3]);
                }
#pragma unroll
            for (int mi = 0; mi < 4; ++mi)
#pragma unroll
                for (int np = 0; np < 2; ++np) {
                    mma16816h(acc16[mi][np * 2],     aL[mi], bR[np][0], bR[np][1]);
                    mma16816h(acc16[mi][np * 2 + 1], aL[mi], bR[np][2], bR[np][3]);
                }
        }
    }

    const int g = lane >> 2, tig = lane & 3;
#pragma unroll
    for (int mi = 0; mi < 4; ++mi) {
#pragma unroll
        for (int np = 0; np < 2; ++np) {
#pragma unroll
            for (int c = 0; c < 2; ++c) {
                int col = bn + wn * 32 + np * 16 + c * 8 + 2 * tig;
                float b0 = bias[col], b1 = bias[col + 1];
                float* a = acc32[mi][np * 2 + c];
                uint32_t* ah = acc16[mi][np * 2 + c];
                __half2 c01 = *reinterpret_cast<__half2*>(&ah[0]);
                __half2 c23 = *reinterpret_cast<__half2*>(&ah[1]);
                int r0 = bm + wm * 64 + mi * 16 + g;
                float v00 = a[0] + __half2float(__low2half(c01))  + b0;
                float v01 = a[1] + __half2float(__high2half(c01)) + b1;
                float v10 = a[2] + __half2float(__low2half(c23))  + b0;
                float v11 = a[3] + __half2float(__high2half(c23)) + b1;
                if (RELU) {
                    v00 = fmaxf(v00, 0.f); v01 = fmaxf(v01, 0.f);
                    v10 = fmaxf(v10, 0.f); v11 = fmaxf(v11, 0.f);
                }
                __half h00 = __float2half_rn(v00), h01 = __float2half_rn(v01);
                __half h10 = __float2half_rn(v10), h11 = __float2half_rn(v11);
                __half l00 = __float2half_rn(v00 - __half2float(h00));
                __half l01 = __float2half_rn(v01 - __half2float(h01));
                __half l10 = __float2half_rn(v10 - __half2float(h10));
                __half l11 = __float2half_rn(v11 - __half2float(h11));
                uint32_t ph0 = (uint32_t)__half_as_ushort(h00) | ((uint32_t)__half_as_ushort(h01) << 16);
                uint32_t pl0 = (uint32_t)__half_as_ushort(l00) | ((uint32_t)__half_as_ushort(l01) << 16);
                uint32_t ph1 = (uint32_t)__half_as_ushort(h10) | ((uint32_t)__half_as_ushort(h11) << 16);
                uint32_t pl1 = (uint32_t)__half_as_ushort(l10) | ((uint32_t)__half_as_ushort(l11) << 16);
                *(uint32_t*)(Oh + (size_t)r0 * strideO + col) = ph0;
                *(uint32_t*)(Ol + (size_t)r0 * strideO + col) = pl0;
                *(uint32_t*)(Oh + (size_t)(r0 + 8) * strideO + col) = ph1;
                *(uint32_t*)(Ol + (size_t)(r0 + 8) * strideO + col) = pl1;
            }
        }
    }
}

// ---------------------------------------------------------------------------
// Small GEMM (gemm3/gemm4): round-11 proven config VERBATIM.
//   128 thr, 4 warps 2x2, warp tile 64x32 (NP=2!), BN=64, 3-stage, f32 accum.
// ---------------------------------------------------------------------------
__device__ __forceinline__ void load_stage4(
        uint32_t sbase, int slot, int k0, int tid,
        const __half* Ah, const __half* Al, const __half* Bh,
        int K, int N, int bm, int bn) {
    const uint32_t dstb = sbase + slot * STAGE_SZ_64;
#pragma unroll
    for (int it = 0; it < 10; ++it) {
        int i = tid + it * 128;
        if (i < 1024) {
            int mat = i >> 9;
            int row = (i >> 2) & 127;
            int seg = i & 3;
            const __half* src = (mat == 0 ? Ah : Al) + (size_t)(bm + row) * K + k0 + seg * 8;
            cp16(dstb + mat * MATSZA + row * PITCH + seg * 16, src, 16);
        } else {
            int j = i - 1024;
            int row = j >> 2;
            int seg = j & 3;
            int n = bn + row;
            const __half* src;
            int size = 16;
            if (n < N) {
                src = Bh + (size_t)n * K + k0 + seg * 8;
            } else {
                src = Bh + k0 + seg * 8;
                size = 0;
            }
            cp16(dstb + 2 * MATSZA + row * PITCH + seg * 16, src, size);
        }
    }
}

template <bool RELU, bool F32OUT>
__global__ void __launch_bounds__(128, 2)
gemm_small(const __half* __restrict__ Ah, const __half* __restrict__ Al,
           const __half* __restrict__ Bh,
           const float* __restrict__ bias,
           __half* __restrict__ Oh, __half* __restrict__ Ol,
           float* __restrict__ Of,
           int K, int N, int strideO) {
    extern __shared__ char smem[];
    const uint32_t sbase = smem_u32(smem);
    const int tid = threadIdx.x;
    const int lane = tid & 31;
    const int wid = tid >> 5;
    const int wm = wid & 1;
    const int wn = wid >> 1;
    const int bm = blockIdx.x * 128;
    const int bn = blockIdx.y * 64;
    const int nk = K >> 5;

    float acc[4][4][4];             // mi x (np*2+c) x 4, NP=2
#pragma unroll
    for (int i = 0; i < 4; ++i)
#pragma unroll
        for (int j = 0; j < 4; ++j)
#pragma unroll
            for (int q = 0; q < 4; ++q) acc[i][j][q] = 0.f;

    const uint32_t a_addr = sbase + (wm * 64 + (lane & 15)) * PITCH + (lane >> 4) * 16;
    const uint32_t b_addr = sbase + 2 * MATSZA +
        (wn * 32 + (lane & 7) + ((lane >> 4) * 8)) * PITCH + ((lane >> 3) & 1) * 16;

    load_stage4(sbase, 0, 0, tid, Ah, Al, Bh, K, N, bm, bn);
    CP_COMMIT();
    if (nk > 1) {
        load_stage4(sbase, 1, 32, tid, Ah, Al, Bh, K, N, bm, bn);
        CP_COMMIT();
    }

    int slot = 0;
    for (int kc = 0; kc < nk; ++kc) {
        if (kc + 1 < nk) { CP_WAIT(1); } else { CP_WAIT(0); }
        __syncthreads();
        if (kc + 2 < nk) {
            int ns = slot + 2; if (ns >= 3) ns -= 3;
            load_stage4(sbase, ns, (kc + 2) * 32, tid, Ah, Al, Bh, K, N, bm, bn);
            CP_COMMIT();
        }
        const uint32_t st = (uint32_t)slot * STAGE_SZ_64;
        if (++slot == 3) slot = 0;
#pragma unroll
        for (int kk = 0; kk < 2; ++kk) {
            const uint32_t ko = kk * 32;
            uint32_t aH[4][4], aL[4][4];
#pragma unroll
            for (int mi = 0; mi < 4; ++mi) {
                LDSM4(aH[mi], a_addr + st + mi * (16 * PITCH) + ko);
                LDSM4(aL[mi], a_addr + st + MATSZA + mi * (16 * PITCH) + ko);
            }
            uint32_t bR[2][4];
#pragma unroll
            for (int np = 0; np < 2; ++np)
                LDSM4(bR[np], b_addr + st + np * (16 * PITCH) + ko);
#pragma unroll
            for (int mi = 0; mi < 4; ++mi)
#pragma unroll
                for (int np = 0; np < 2; ++np) {
                    mma16816(acc[mi][np * 2],     aH[mi], bR[np][0], bR[np][1]);
                    mma16816(acc[mi][np * 2 + 1], aH[mi], bR[np][2], bR[np][3]);
                }
#pragma unroll
            for (int mi = 0; mi < 4; ++mi)
#pragma unroll
                for (int np = 0; np < 2; ++np) {
                    mma16816(acc[mi][np * 2],     aL[mi], bR[np][0], bR[np][1]);
                    mma16816(acc[mi][np * 2 + 1], aL[mi], bR[np][2], bR[np][3]);
                }
        }
    }

    const int g = lane >> 2, tig = lane & 3;
#pragma unroll
    for (int mi = 0; mi < 4; ++mi) {
#pragma unroll
        for (int np = 0; np < 2; ++np) {
#pragma unroll
            for (int c = 0; c < 2; ++c) {
                int col = bn + wn * 32 + np * 16 + c * 8 + 2 * tig;
                float b0 = 0.f, b1 = 0.f;
                if (col < N) { b0 = bias[col]; b1 = bias[col + 1]; }
                float* a = acc[mi][np * 2 + c];
                int r0 = bm + wm * 64 + mi * 16 + g;
                float v00 = a[0] + b0, v01 = a[1] + b1;
                float v10 = a[2] + b0, v11 = a[3] + b1;
                if (RELU) {
                    v00 = fmaxf(v00, 0.f); v01 = fmaxf(v01, 0.f);
                    v10 = fmaxf(v10, 0.f); v11 = fmaxf(v11, 0.f);
                }
                if (F32OUT) {
                    if (col < N) {
                        *(float2*)(Of + (size_t)r0 * strideO + col) = make_float2(v00, v01);
                        *(float2*)(Of + (size_t)(r0 + 8) * strideO + col) = make_float2(v10, v11);
                    }
                } else {
                    __half h00 = __float2half_rn(v00), h01 = __float2half_rn(v01);
                    __half h10 = __float2half_rn(v10), h11 = __float2half_rn(v11);
                    __half l00 = __float2half_rn(v00 - __half2float(h00));
                    __half l01 = __float2half_rn(v01 - __half2float(h01));
                    __half l10 = __float2half_rn(v10 - __half2float(h10));
                    __half l11 = __float2half_rn(v11 - __half2float(h11));
                    uint32_t ph0 = (uint32_t)__half_as_ushort(h00) | ((uint32_t)__half_as_ushort(h01) << 16);
                    uint32_t pl0 = (uint32_t)__half_as_ushort(l00) | ((uint32_t)__half_as_ushort(l01) << 16);
                    uint32_t ph1 = (uint32_t)__half_as_ushort(h10) | ((uint32_t)__half_as_ushort(h11) << 16);
                    uint32_t pl1 = (uint32_t)__half_as_ushort(l10) | ((uint32_t)__half_as_ushort(l11) << 16);
                    *(uint32_t*)(Oh + (size_t)r0 * strideO + col) = ph0;
                    *(uint32_t*)(Ol + (size_t)r0 * strideO + col) = pl0;
                    *(uint32_t*)(Oh + (size_t)(r0 + 8) * strideO + col) = ph1;
                    *(uint32_t*)(Ol + (size_t)(r0 + 8) * strideO + col) = pl1;
                }
            }
        }
    }
}

// ---------------------------------------------------------------------------
extern "C" void kernel_launch(void* const* d_in, const int* in_sizes, int n_in,
                              void* d_out, int out_size) {
    const float* x    = (const float*)d_in[0];
    const float* h0   = (const float*)d_in[1];
    const float* W_ih = (const float*)d_in[2];
    const float* W_hh = (const float*)d_in[3];
    const float* b_ih = (const float*)d_in[4];
    const float* b_hh = (const float*)d_in[5];
    const float* w1   = (const float*)d_in[6];
    const float* b1   = (const float*)d_in[7];
    const float* w2   = (const float*)d_in[8];
    const float* b2   = (const float*)d_in[9];
    const float* w3   = (const float*)d_in[10];
    const float* b3   = (const float*)d_in[11];
    const float* w4   = (const float*)d_in[12];
    const float* b4   = (const float*)d_in[13];
    float* out = (float*)d_out;
    float* hid = (out_size >= B_ * T_ + B_) ? out + (size_t)B_ * T_ : nullptr;

    __half *ath, *atl, *w1h, *w2h, *w3h, *w4h;
    __half *y1h, *y1l, *y2h, *y2l, *y3h, *y3l;
    cudaGetSymbolAddress((void**)&ath, g_ath); cudaGetSymbolAddress((void**)&atl, g_atl);
    cudaGetSymbolAddress((void**)&w1h, g_w1h); cudaGetSymbolAddress((void**)&w2h, g_w2h);
    cudaGetSymbolAddress((void**)&w3h, g_w3h); cudaGetSymbolAddress((void**)&w4h, g_w4h);
    cudaGetSymbolAddress((void**)&y1h, g_y1h); cudaGetSymbolAddress((void**)&y1l, g_y1l);
    cudaGetSymbolAddress((void**)&y2h, g_y2h); cudaGetSymbolAddress((void**)&y2l, g_y2l);
    cudaGetSymbolAddress((void**)&y3h, g_y3h); cudaGetSymbolAddress((void**)&y3l, g_y3l);

    cudaFuncSetAttribute(gemm_big<true>,           cudaFuncAttributeMaxDynamicSharedMemorySize, SMEM_128_2);
    cudaFuncSetAttribute(gemm_small<true,  false>, cudaFuncAttributeMaxDynamicSharedMemorySize, SMEM_64_3);
    cudaFuncSetAttribute(gemm_small<false, true >, cudaFuncAttributeMaxDynamicSharedMemorySize, SMEM_64_3);

    // 1) input projection
    proj_kernel<<<dim3((T_ + 31) / 32, B_ / 32), 256>>>(x, W_ih, b_ih, b_hh);
    // 2) recurrence (hidden -> out tail)
    scan_kernel<<<B_ / 256, 256>>>(h0, W_hh, hid);
    // 3) weight conversions
    cvt_all<<<dim3((D1_ * T_ + 255) / 256, 4), 256>>>(w1, w2, w3, w4);
    // 4) y1 = relu(hsT @ w1^T + b1)   (capture slot: gemm_big)
    gemm_big<true><<<dim3(B_ / 128, D1_ / 128), 256, SMEM_128_2>>>(
        ath, atl, w1h, b1, y1h, y1l, TPAD, D1_, D1_);
    // 5) y2 = relu(y1 @ w2^T + b2)
    gemm_big<true><<<dim3(B_ / 128, D2_ / 128), 256, SMEM_128_2>>>(
        y1h, y1l, w2h, b2, y2h, y2l, D1_, D2_, D2_);
    // 6) y3 = relu(y2 @ w3^T + b3)
    gemm_small<true, false><<<dim3(B_ / 128, D3_ / 64), 128, SMEM_64_3>>>(
        y2h, y2l, w3h, b3, y3h, y3l, nullptr, D2_, D3_, D3_);
    // 7) out = y3 @ w4^T + b4
    gemm_small<false, true><<<dim3(B_ / 128, (T_ + 63) / 64), 128, SMEM_64_3>>>(
        y3h, y3l, w4h, b4, nullptr, nullptr, out, D3_, T_, T_);
}

// round 14
// speedup vs baseline: 1.5323x; 1.5323x over previous
#include <cuda_runtime.h>
#include <cuda_fp16.h>
#include <cstdint>

// ---------------------------------------------------------------------------
// Problem constants
// ---------------------------------------------------------------------------
constexpr int B_   = 8192;
constexpr int T_   = 658;
constexpr int I_   = 7;
constexpr int D1_  = 1024;
constexpr int D2_  = 512;
constexpr int D3_  = 128;
constexpr int XWT  = 688;
constexpr int TPAD = 672;

// ---------------------------------------------------------------------------
// Scratch (single fp16 everywhere now)
// ---------------------------------------------------------------------------
__device__ float   g_xw [(size_t)XWT * B_];
__device__ __half  g_at [(size_t)B_ * TPAD];    // hs^T [B,TPAD] fp16

__device__ __half  g_w1h[(size_t)D1_ * TPAD];
__device__ __half  g_w2h[(size_t)D2_ * D1_ ];
__device__ __half  g_w3h[(size_t)D3_ * D2_ ];
__device__ __half  g_w4h[(size_t)T_  * D3_ ];

__device__ __half  g_y1 [(size_t)B_ * D1_];
__device__ __half  g_y2 [(size_t)B_ * D2_];
__device__ __half  g_y3 [(size_t)B_ * D3_];

// ---------------------------------------------------------------------------
// PTX helpers
// ---------------------------------------------------------------------------
__device__ __forceinline__ uint32_t smem_u32(const void* p) {
    uint32_t a;
    asm("{ .reg .u64 t; cvta.to.shared.u64 t, %1; cvt.u32.u64 %0, t; }" : "=r"(a) : "l"(p));
    return a;
}

__device__ __forceinline__ void cp16(uint32_t dst, const void* src, int srcsize) {
    asm volatile("cp.async.cg.shared.global [%0], [%1], 16, %2;"
                 :: "r"(dst), "l"(src), "r"(srcsize));
}
#define CP_COMMIT() asm volatile("cp.async.commit_group;" ::: "memory")
#define CP_WAIT(n)  asm volatile("cp.async.wait_group %0;" :: "n"(n) : "memory")

#define LDSM4(r, a)                                                             \
    asm volatile("ldmatrix.sync.aligned.m8n8.x4.shared.b16 {%0,%1,%2,%3}, [%4];"\
                 : "=r"((r)[0]), "=r"((r)[1]), "=r"((r)[2]), "=r"((r)[3])       \
                 : "r"(a))

__device__ __forceinline__ void mma16816(float* d, const uint32_t* a,
                                         uint32_t b0, uint32_t b1) {
    asm volatile("mma.sync.aligned.m16n8k16.row.col.f32.f16.f16.f32 "
                 "{%0,%1,%2,%3}, {%4,%5,%6,%7}, {%8,%9}, {%0,%1,%2,%3};"
                 : "+f"(d[0]), "+f"(d[1]), "+f"(d[2]), "+f"(d[3])
                 : "r"(a[0]), "r"(a[1]), "r"(a[2]), "r"(a[3]), "r"(b0), "r"(b1));
}

// ---------------------------------------------------------------------------
// Stage 1: projection ([T,B] fp32)
// ---------------------------------------------------------------------------
__global__ void proj_kernel(const float* __restrict__ x,
                            const float* __restrict__ W_ih,
                            const float* __restrict__ b_ih,
                            const float* __restrict__ b_hh) {
    __shared__ float xs[32][225];
    const int t0 = blockIdx.x * 32;
    const int b0 = blockIdx.y * 32;
    const int tid = threadIdx.x;
    const int tlim = min(32, T_ - t0);
    const int nfl = tlim * I_;

    for (int i = tid; i < 32 * 224; i += 256) {
        int bl = i / 224;
        int off = i - bl * 224;
        float v = 0.f;
        if (off < nfl) v = x[((size_t)(b0 + bl) * T_ + t0) * I_ + off];
        xs[bl][off] = v;
    }
    __syncthreads();

    float w[7];
#pragma unroll
    for (int j = 0; j < 7; ++j) w[j] = W_ih[j];
    const float bias = b_ih[0] + b_hh[0];

    for (int i = tid; i < 1024; i += 256) {
        int bl = i & 31;
        int tl = i >> 5;
        if (tl < tlim) {
            const float* row = &xs[bl][tl * 7];
            float s = bias;
#pragma unroll
            for (int j = 0; j < 7; ++j) s = fmaf(row[j], w[j], s);
            g_xw[(size_t)(t0 + tl) * B_ + (b0 + bl)] = s;
        }
    }
}

// ---------------------------------------------------------------------------
// Stage 2: tanh recurrence -> g_at [B,TPAD] single fp16
// ---------------------------------------------------------------------------
__device__ __forceinline__ float tanh_fast(float xv) {
    float ax = fabsf(xv);
    float e = __expf(-2.0f * ax);
    float r = __fdividef(1.0f - e, 1.0f + e);
    return copysignf(r, xv);
}

__global__ void __launch_bounds__(256)
scan_kernel(const float* __restrict__ h0,
            const float* __restrict__ W_hh,
            float* __restrict__ hid) {
    __shared__ uint32_t sh[256][17];   // 16 packed fp16x2 per thread + pad
    const int tid = threadIdx.x;
    const int b0 = blockIdx.x * 256;
    const int b  = b0 + tid;

    const float whh = W_hh[0];
    const float* xp = g_xw + b;
    float h = h0[b];
    float hT = h;

    float bufA[16], bufB[16];
#pragma unroll
    for (int j = 0; j < 16; ++j) bufA[j] = xp[(size_t)j * B_];

    for (int tc = 0; tc < TPAD; tc += 32) {
        uint32_t pk = 0;
#pragma unroll
        for (int j = 0; j < 16; ++j) bufB[j] = xp[(size_t)(tc + 16 + j) * B_];
#pragma unroll
        for (int j = 0; j < 16; ++j) {
            h = tanh_fast(fmaf(h, whh, bufA[j]));
            uint32_t hb = (uint32_t)__half_as_ushort(__float2half_rn(h));
            if (j & 1) { pk |= hb << 16; sh[tid][j >> 1] = pk; }
            else       { pk = hb; }
            if (tc + j == T_ - 1) hT = h;
        }
#pragma unroll
        for (int j = 0; j < 16; ++j) bufA[j] = xp[(size_t)(tc + 32 + j) * B_];  // max 687 < XWT
#pragma unroll
        for (int j = 0; j < 16; ++j) {
            h = tanh_fast(fmaf(h, whh, bufB[j]));
            uint32_t hb = (uint32_t)__half_as_ushort(__float2half_rn(h));
            if (j & 1) { pk |= hb << 16; sh[tid][8 + (j >> 1)] = pk; }
            else       { pk = hb; }
            if (tc + 16 + j == T_ - 1) hT = h;
        }
        __syncthreads();
        // flush: 256 rows x 16 words, coalesced along t
#pragma unroll
        for (int it = 0; it < 16; ++it) {
            int lin = it * 256 + tid;
            int r = lin >> 4;
            int p = lin & 15;
            *(uint32_t*)(g_at + (size_t)(b0 + r) * TPAD + tc + 2 * p) = sh[r][p];
        }
        __syncthreads();
    }
    if (hid) hid[b] = hT;
}

// ---------------------------------------------------------------------------
// Weight conversion
// ---------------------------------------------------------------------------
__device__ __forceinline__ void cvt_seg(const float* __restrict__ src,
                                        __half* __restrict__ hi,
                                        int R, int K, int Kp, int i) {
    if (i < R * K) {
        int r = i / K, k = i - r * K;
        hi[(size_t)r * Kp + k] = __float2half_rn(src[i]);
    }
}

__global__ void cvt_all(const float* __restrict__ w1, const float* __restrict__ w2,
                        const float* __restrict__ w3, const float* __restrict__ w4) {
    int i = blockIdx.x * 256 + threadIdx.x;
    switch (blockIdx.y) {
        case 0: cvt_seg(w1, g_w1h, D1_, T_,  TPAD, i); break;
        case 1: cvt_seg(w2, g_w2h, D2_, D1_, D1_,  i); break;
        case 2: cvt_seg(w3, g_w3h, D3_, D2_, D2_,  i); break;
        case 3: cvt_seg(w4, g_w4h, T_,  D3_, D3_,  i); break;
    }
}

// ---------------------------------------------------------------------------
// mma.sync GEMM: C[M,N] = act(A * B^T + bias), single fp16 A x fp16 B.
//   CTA 128 x (2*WN), BK=32, 4 warps (2x2), warp tile 64 x WN.
//   3-stage cp.async, 2 CTAs/SM.
// ---------------------------------------------------------------------------
constexpr int PITCH   = 80;
constexpr int MATSZA  = 128 * PITCH;                     // 10240 (A only)
constexpr int STG_128 = MATSZA + 128 * PITCH;            // 20480
constexpr int STG_64  = MATSZA +  64 * PITCH;            // 15360
constexpr int SM_128  = 3 * STG_128;                     // 61440
constexpr int SM_64   = 3 * STG_64;                      // 46080

template <int BN>
__device__ __forceinline__ void load_stage(
        uint32_t sbase, int slot, int k0, int tid,
        const __half* A, const __half* Bh,
        int K, int N, int bm, int bn) {
    constexpr int SSZ = (BN == 128) ? STG_128 : STG_64;
    const uint32_t dstb = sbase + slot * SSZ;
#pragma unroll
    for (int it = 0; it < (128 + BN) * 4 / 128; ++it) {
        int i = tid + it * 128;
        if (i < 512) {
            int row = i >> 2;
            int seg = i & 3;
            const __half* src = A + (size_t)(bm + row) * K + k0 + seg * 8;
            cp16(dstb + row * PITCH + seg * 16, src, 16);
        } else {
            int j = i - 512;
            int row = j >> 2;              // 0..BN-1
            int seg = j & 3;
            int n = bn + row;
            const __half* src;
            int size = 16;
            if (n < N) {
                src = Bh + (size_t)n * K + k0 + seg * 8;
            } else {
                src = Bh + k0 + seg * 8;
                size = 0;
            }
            cp16(dstb + MATSZA + row * PITCH + seg * 16, src, size);
        }
    }
}

template <int WN, bool RELU, bool F32OUT>
__global__ void __launch_bounds__(128, 2)
gemm_mma(const __half* __restrict__ A, const __half* __restrict__ Bh,
         const float* __restrict__ bias,
         __half* __restrict__ O, float* __restrict__ Of,
         int K, int N, int strideO) {
    constexpr int BN = 2 * WN;
    constexpr int NP = WN / 16;
    constexpr int SSZ = (BN == 128) ? STG_128 : STG_64;
    extern __shared__ char smem[];
    const uint32_t sbase = smem_u32(smem);
    const int tid = threadIdx.x;
    const int lane = tid & 31;
    const int wid = tid >> 5;
    const int wm = wid & 1;
    const int wn = wid >> 1;
    const int bm = blockIdx.x * 128;
    const int bn = blockIdx.y * BN;
    const int nk = K >> 5;

    float acc[4][2 * NP][4];
#pragma unroll
    for (int i = 0; i < 4; ++i)
#pragma unroll
        for (int j = 0; j < 2 * NP; ++j)
#pragma unroll
            for (int q = 0; q < 4; ++q) acc[i][j][q] = 0.f;

    const uint32_t a_addr = sbase + (wm * 64 + (lane & 15)) * PITCH + (lane >> 4) * 16;
    const uint32_t b_addr = sbase + MATSZA +
        (wn * WN + (lane & 7) + ((lane >> 4) * 8)) * PITCH + ((lane >> 3) & 1) * 16;

    load_stage<BN>(sbase, 0, 0, tid, A, Bh, K, N, bm, bn);
    CP_COMMIT();
    if (nk > 1) {
        load_stage<BN>(sbase, 1, 32, tid, A, Bh, K, N, bm, bn);
        CP_COMMIT();
    }

    int slot = 0;
    for (int kc = 0; kc < nk; ++kc) {
        if (kc + 1 < nk) { CP_WAIT(1); } else { CP_WAIT(0); }
        __syncthreads();
        if (kc + 2 < nk) {
            int ns = slot + 2; if (ns >= 3) ns -= 3;
            load_stage<BN>(sbase, ns, (kc + 2) * 32, tid, A, Bh, K, N, bm, bn);
            CP_COMMIT();
        }
        const uint32_t st = (uint32_t)slot * SSZ;
        if (++slot == 3) slot = 0;
#pragma unroll
        for (int kk = 0; kk < 2; ++kk) {
            const uint32_t ko = kk * 32;
            uint32_t aR[4][4];
#pragma unroll
            for (int mi = 0; mi < 4; ++mi)
                LDSM4(aR[mi], a_addr + st + mi * (16 * PITCH) + ko);
            uint32_t bR[NP][4];
#pragma unroll
            for (int np = 0; np < NP; ++np)
                LDSM4(bR[np], b_addr + st + np * (16 * PITCH) + ko);
#pragma unroll
            for (int mi = 0; mi < 4; ++mi)
#pragma unroll
                for (int np = 0; np < NP; ++np) {
                    mma16816(acc[mi][np * 2],     aR[mi], bR[np][0], bR[np][1]);
                    mma16816(acc[mi][np * 2 + 1], aR[mi], bR[np][2], bR[np][3]);
                }
        }
    }

    // Epilogue
    const int g = lane >> 2, tig = lane & 3;
#pragma unroll
    for (int mi = 0; mi < 4; ++mi) {
#pragma unroll
        for (int np = 0; np < NP; ++np) {
#pragma unroll
            for (int c = 0; c < 2; ++c) {
                int col = bn + wn * WN + np * 16 + c * 8 + 2 * tig;
                float b0 = 0.f, b1 = 0.f;
                if (col < N) { b0 = bias[col]; b1 = bias[col + 1]; }
                float* a = acc[mi][np * 2 + c];
                int r0 = bm + wm * 64 + mi * 16 + g;
                float v00 = a[0] + b0, v01 = a[1] + b1;
                float v10 = a[2] + b0, v11 = a[3] + b1;
                if (RELU) {
                    v00 = fmaxf(v00, 0.f); v01 = fmaxf(v01, 0.f);
                    v10 = fmaxf(v10, 0.f); v11 = fmaxf(v11, 0.f);
                }
                if (F32OUT) {
                    if (col < N) {
                        *(float2*)(Of + (size_t)r0 * strideO + col) = make_float2(v00, v01);
                        *(float2*)(Of + (size_t)(r0 + 8) * strideO + col) = make_float2(v10, v11);
                    }
                } else {
                    __half h00 = __float2half_rn(v00), h01 = __float2half_rn(v01);
                    __half h10 = __float2half_rn(v10), h11 = __float2half_rn(v11);
                    uint32_t p0 = (uint32_t)__half_as_ushort(h00) | ((uint32_t)__half_as_ushort(h01) << 16);
                    uint32_t p1 = (uint32_t)__half_as_ushort(h10) | ((uint32_t)__half_as_ushort(h11) << 16);
                    *(uint32_t*)(O + (size_t)r0 * strideO + col) = p0;
                    *(uint32_t*)(O + (size_t)(r0 + 8) * strideO + col) = p1;
                }
            }
        }
    }
}

// ---------------------------------------------------------------------------
extern "C" void kernel_launch(void* const* d_in, const int* in_sizes, int n_in,
                              void* d_out, int out_size) {
    const float* x    = (const float*)d_in[0];
    const float* h0   = (const float*)d_in[1];
    const float* W_ih = (const float*)d_in[2];
    const float* W_hh = (const float*)d_in[3];
    const float* b_ih = (const float*)d_in[4];
    const float* b_hh = (const float*)d_in[5];
    const float* w1   = (const float*)d_in[6];
    const float* b1   = (const float*)d_in[7];
    const float* w2   = (const float*)d_in[8];
    const float* b2   = (const float*)d_in[9];
    const float* w3   = (const float*)d_in[10];
    const float* b3   = (const float*)d_in[11];
    const float* w4   = (const float*)d_in[12];
    const float* b4   = (const float*)d_in[13];
    float* out = (float*)d_out;
    float* hid = (out_size >= B_ * T_ + B_) ? out + (size_t)B_ * T_ : nullptr;

    __half *at, *w1h, *w2h, *w3h, *w4h, *y1, *y2, *y3;
    cudaGetSymbolAddress((void**)&at,  g_at);
    cudaGetSymbolAddress((void**)&w1h, g_w1h); cudaGetSymbolAddress((void**)&w2h, g_w2h);
    cudaGetSymbolAddress((void**)&w3h, g_w3h); cudaGetSymbolAddress((void**)&w4h, g_w4h);
    cudaGetSymbolAddress((void**)&y1,  g_y1);  cudaGetSymbolAddress((void**)&y2,  g_y2);
    cudaGetSymbolAddress((void**)&y3,  g_y3);

    cudaFuncSetAttribute(gemm_mma<64, true,  false>, cudaFuncAttributeMaxDynamicSharedMemorySize, SM_128);
    cudaFuncSetAttribute(gemm_mma<32, true,  false>, cudaFuncAttributeMaxDynamicSharedMemorySize, SM_64);
    cudaFuncSetAttribute(gemm_mma<32, false, true >, cudaFuncAttributeMaxDynamicSharedMemorySize, SM_64);

    // 1) input projection
    proj_kernel<<<dim3((T_ + 31) / 32, B_ / 32), 256>>>(x, W_ih, b_ih, b_hh);
    // 2) recurrence -> g_at [B,TPAD] fp16, hidden -> out tail
    scan_kernel<<<B_ / 256, 256>>>(h0, W_hh, hid);
    // 3) weight conversions
    cvt_all<<<dim3((D1_ * T_ + 255) / 256, 4), 256>>>(w1, w2, w3, w4);
    // 4) y1 = relu(hsT @ w1^T + b1)   M=8192 N=1024 K=672, BN=128
    gemm_mma<64, true, false><<<dim3(B_ / 128, D1_ / 128), 128, SM_128>>>(
        at, w1h, b1, y1, nullptr, TPAD, D1_, D1_);
    // 5) y2 = relu(y1 @ w2^T + b2)    K=1024, BN=128
    gemm_mma<64, true, false><<<dim3(B_ / 128, D2_ / 128), 128, SM_128>>>(
        y1, w2h, b2, y2, nullptr, D1_, D2_, D2_);
    // 6) y3 = relu(y2 @ w3^T + b3)    K=512, BN=64
    gemm_mma<32, true, false><<<dim3(B_ / 128, D3_ / 64), 128, SM_64>>>(
        y2, w3h, b3, y3, nullptr, D2_, D3_, D3_);
    // 7) out = y3 @ w4^T + b4         K=128, N=658, BN=64
    gemm_mma<32, false, true><<<dim3(B_ / 128, (T_ + 63) / 64), 128, SM_64>>>(
        y3, w4h, b4, nullptr, out, D3_, T_, T_);
}